// round 4
// baseline (speedup 1.0000x reference)
#include <cuda_runtime.h>
#include <cuda_bf16.h>

#define B_ROWS 16384
#define NCLASS 1000
#define DIM 1024
#define WARPS_PER_BLOCK 8
#define THREADS (WARPS_PER_BLOCK * 32)
#define NBLOCKS (B_ROWS / WARPS_PER_BLOCK)   // 2048

__device__ float g_partials[NBLOCKS];

// One warp per row: compute x.x, c.c, x.c over D=1024 with float4 loads.
__global__ __launch_bounds__(THREADS) void proximity_main_kernel(
    const float* __restrict__ x,
    const int* __restrict__ labels,
    const float* __restrict__ centers)
{
    const int warp = threadIdx.x >> 5;
    const int lane = threadIdx.x & 31;
    const int row  = blockIdx.x * WARPS_PER_BLOCK + warp;

    const float4* __restrict__ xr =
        reinterpret_cast<const float4*>(x + (size_t)row * DIM);
    int lab = labels[row];
    // Defensive clamp: never fault even if dtype assumption is off.
    lab = min(max(lab, 0), NCLASS - 1);
    const float4* __restrict__ cr =
        reinterpret_cast<const float4*>(centers + (size_t)lab * DIM);

    float sxx = 0.f, scc = 0.f, sxc = 0.f;
    // 1024 floats = 256 float4 per row; 32 lanes * 8 iterations.
    #pragma unroll
    for (int i = 0; i < 8; ++i) {
        float4 xv = xr[lane + 32 * i];
        float4 cv = cr[lane + 32 * i];
        sxx = fmaf(xv.x, xv.x, sxx);
        sxx = fmaf(xv.y, xv.y, sxx);
        sxx = fmaf(xv.z, xv.z, sxx);
        sxx = fmaf(xv.w, xv.w, sxx);
        scc = fmaf(cv.x, cv.x, scc);
        scc = fmaf(cv.y, cv.y, scc);
        scc = fmaf(cv.z, cv.z, scc);
        scc = fmaf(cv.w, cv.w, scc);
        sxc = fmaf(xv.x, cv.x, sxc);
        sxc = fmaf(xv.y, cv.y, sxc);
        sxc = fmaf(xv.z, cv.z, sxc);
        sxc = fmaf(xv.w, cv.w, sxc);
    }

    // Warp reduction of the three sums.
    #pragma unroll
    for (int off = 16; off > 0; off >>= 1) {
        sxx += __shfl_down_sync(0xFFFFFFFFu, sxx, off);
        scc += __shfl_down_sync(0xFFFFFFFFu, scc, off);
        sxc += __shfl_down_sync(0xFFFFFFFFu, sxc, off);
    }

    __shared__ float s_dist[WARPS_PER_BLOCK];
    if (lane == 0) {
        const float eps = 1e-12f;
        float nx = fmaxf(sqrtf(sxx), eps);
        float nc = fmaxf(sqrtf(scc), eps);
        // dist = ||xn||^2 + ||cn||^2 - 2 xn.cn
        float d = sxx / (nx * nx) + scc / (nc * nc) - 2.0f * sxc / (nx * nc);
        d = fminf(fmaxf(d, 1e-12f), 1e12f);
        s_dist[warp] = d;
    }
    __syncthreads();
    if (threadIdx.x == 0) {
        float s = 0.f;
        #pragma unroll
        for (int w = 0; w < WARPS_PER_BLOCK; ++w) s += s_dist[w];
        g_partials[blockIdx.x] = s;
    }
}

// Single-block final reduction of 2048 partials -> mean.
__global__ __launch_bounds__(256) void proximity_reduce_kernel(float* __restrict__ out)
{
    __shared__ float sm[256];
    float s = 0.f;
    for (int i = threadIdx.x; i < NBLOCKS; i += 256) s += g_partials[i];
    sm[threadIdx.x] = s;
    __syncthreads();
    #pragma unroll
    for (int stride = 128; stride > 0; stride >>= 1) {
        if (threadIdx.x < stride) sm[threadIdx.x] += sm[threadIdx.x + stride];
        __syncthreads();
    }
    if (threadIdx.x == 0) out[0] = sm[0] * (1.0f / (float)B_ROWS);
}

extern "C" void kernel_launch(void* const* d_in, const int* in_sizes, int n_in,
                              void* d_out, int out_size)
{
    const float* x       = (const float*)d_in[0];
    const int*   labels  = (const int*)d_in[1];
    const float* centers = (const float*)d_in[2];
    float*       out     = (float*)d_out;

    proximity_main_kernel<<<NBLOCKS, THREADS>>>(x, labels, centers);
    proximity_reduce_kernel<<<1, 256>>>(out);
}

// round 5
// speedup vs baseline: 1.0133x; 1.0133x over previous
#include <cuda_runtime.h>
#include <cuda_bf16.h>

#define B_ROWS 16384
#define NCLASS 1000
#define DIM 1024
#define WARPS_PER_BLOCK 8
#define THREADS (WARPS_PER_BLOCK * 32)
#define NBLOCKS (B_ROWS / WARPS_PER_BLOCK)   // 2048

__device__ float g_partials[NBLOCKS];
__device__ unsigned int g_count;   // zero-initialized at module load; reset each run

// One warp per row: x.x, c.c, x.c over D=1024 with float4 loads.
// Last block to finish performs the deterministic final reduction.
__global__ __launch_bounds__(THREADS) void proximity_fused_kernel(
    const float* __restrict__ x,
    const int* __restrict__ labels,
    const float* __restrict__ centers,
    float* __restrict__ out)
{
    const int warp = threadIdx.x >> 5;
    const int lane = threadIdx.x & 31;
    const int row  = blockIdx.x * WARPS_PER_BLOCK + warp;

    const float4* __restrict__ xr =
        reinterpret_cast<const float4*>(x + (size_t)row * DIM);
    int lab = labels[row];
    lab = min(max(lab, 0), NCLASS - 1);   // defensive: never fault
    const float4* __restrict__ cr =
        reinterpret_cast<const float4*>(centers + (size_t)lab * DIM);

    float sxx = 0.f, scc = 0.f, sxc = 0.f;
    #pragma unroll
    for (int i = 0; i < 8; ++i) {
        float4 xv = xr[lane + 32 * i];
        float4 cv = cr[lane + 32 * i];
        sxx = fmaf(xv.x, xv.x, sxx);
        sxx = fmaf(xv.y, xv.y, sxx);
        sxx = fmaf(xv.z, xv.z, sxx);
        sxx = fmaf(xv.w, xv.w, sxx);
        scc = fmaf(cv.x, cv.x, scc);
        scc = fmaf(cv.y, cv.y, scc);
        scc = fmaf(cv.z, cv.z, scc);
        scc = fmaf(cv.w, cv.w, scc);
        sxc = fmaf(xv.x, cv.x, sxc);
        sxc = fmaf(xv.y, cv.y, sxc);
        sxc = fmaf(xv.z, cv.z, sxc);
        sxc = fmaf(xv.w, cv.w, sxc);
    }

    #pragma unroll
    for (int off = 16; off > 0; off >>= 1) {
        sxx += __shfl_down_sync(0xFFFFFFFFu, sxx, off);
        scc += __shfl_down_sync(0xFFFFFFFFu, scc, off);
        sxc += __shfl_down_sync(0xFFFFFFFFu, sxc, off);
    }

    __shared__ float s_dist[WARPS_PER_BLOCK];
    if (lane == 0) {
        const float eps = 1e-12f;
        float nx = fmaxf(sqrtf(sxx), eps);
        float nc = fmaxf(sqrtf(scc), eps);
        float d = sxx / (nx * nx) + scc / (nc * nc) - 2.0f * sxc / (nx * nc);
        d = fminf(fmaxf(d, 1e-12f), 1e12f);
        s_dist[warp] = d;
    }
    __syncthreads();

    __shared__ bool s_last;
    if (threadIdx.x == 0) {
        float s = 0.f;
        #pragma unroll
        for (int w = 0; w < WARPS_PER_BLOCK; ++w) s += s_dist[w];
        g_partials[blockIdx.x] = s;
        __threadfence();  // make partial visible before ticketing
        unsigned int ticket = atomicAdd(&g_count, 1u);
        s_last = (ticket == NBLOCKS - 1);
    }
    __syncthreads();

    if (s_last) {
        // Deterministic final reduction over 2048 partials (L2-resident).
        __shared__ float sm[THREADS];
        float s = 0.f;
        #pragma unroll
        for (int i = threadIdx.x; i < NBLOCKS; i += THREADS) s += g_partials[i];
        sm[threadIdx.x] = s;
        __syncthreads();
        #pragma unroll
        for (int stride = THREADS / 2; stride > 0; stride >>= 1) {
            if (threadIdx.x < stride) sm[threadIdx.x] += sm[threadIdx.x + stride];
            __syncthreads();
        }
        if (threadIdx.x == 0) {
            out[0] = sm[0] * (1.0f / (float)B_ROWS);
            g_count = 0;  // reset for next graph replay
        }
    }
}

extern "C" void kernel_launch(void* const* d_in, const int* in_sizes, int n_in,
                              void* d_out, int out_size)
{
    const float* x       = (const float*)d_in[0];
    const int*   labels  = (const int*)d_in[1];
    const float* centers = (const float*)d_in[2];
    float*       out     = (float*)d_out;

    proximity_fused_kernel<<<NBLOCKS, THREADS>>>(x, labels, centers, out);
}

// round 6
// speedup vs baseline: 1.1530x; 1.1379x over previous
#include <cuda_runtime.h>
#include <cuda_bf16.h>

#define B_ROWS 16384
#define NCLASS 1000
#define DIM 1024
#define WARPS_PER_BLOCK 8
#define THREADS (WARPS_PER_BLOCK * 32)
#define NBLOCKS (B_ROWS / WARPS_PER_BLOCK)   // 2048

__device__ float g_partials[NBLOCKS];
__device__ unsigned int g_count;   // zero at load; reset each run -> graph-replay safe

// One warp per row. All 16 float4 loads issued before any FMA -> MLP=16/thread.
__global__ __launch_bounds__(THREADS) void proximity_fused_kernel(
    const float* __restrict__ x,
    const int* __restrict__ labels,
    const float* __restrict__ centers,
    float* __restrict__ out)
{
    const int warp = threadIdx.x >> 5;
    const int lane = threadIdx.x & 31;
    const int row  = blockIdx.x * WARPS_PER_BLOCK + warp;

    // Issue the label load first (dependent chain head).
    int lab = labels[row];

    const float4* __restrict__ xr =
        reinterpret_cast<const float4*>(x + (size_t)row * DIM);

    // Front-batch the 8 x loads (DRAM stream) immediately — they don't depend on lab.
    float4 xv[8];
    #pragma unroll
    for (int i = 0; i < 8; ++i) xv[i] = xr[lane + 32 * i];

    lab = min(max(lab, 0), NCLASS - 1);   // defensive clamp
    const float4* __restrict__ cr =
        reinterpret_cast<const float4*>(centers + (size_t)lab * DIM);

    // Front-batch the 8 center loads (L2-resident gather).
    float4 cv[8];
    #pragma unroll
    for (int i = 0; i < 8; ++i) cv[i] = cr[lane + 32 * i];

    float sxx = 0.f, scc = 0.f, sxc = 0.f;
    #pragma unroll
    for (int i = 0; i < 8; ++i) {
        sxx = fmaf(xv[i].x, xv[i].x, sxx);
        sxx = fmaf(xv[i].y, xv[i].y, sxx);
        sxx = fmaf(xv[i].z, xv[i].z, sxx);
        sxx = fmaf(xv[i].w, xv[i].w, sxx);
        scc = fmaf(cv[i].x, cv[i].x, scc);
        scc = fmaf(cv[i].y, cv[i].y, scc);
        scc = fmaf(cv[i].z, cv[i].z, scc);
        scc = fmaf(cv[i].w, cv[i].w, scc);
        sxc = fmaf(xv[i].x, cv[i].x, sxc);
        sxc = fmaf(xv[i].y, cv[i].y, sxc);
        sxc = fmaf(xv[i].z, cv[i].z, sxc);
        sxc = fmaf(xv[i].w, cv[i].w, sxc);
    }

    #pragma unroll
    for (int off = 16; off > 0; off >>= 1) {
        sxx += __shfl_down_sync(0xFFFFFFFFu, sxx, off);
        scc += __shfl_down_sync(0xFFFFFFFFu, scc, off);
        sxc += __shfl_down_sync(0xFFFFFFFFu, sxc, off);
    }

    __shared__ float s_dist[WARPS_PER_BLOCK];
    if (lane == 0) {
        const float eps = 1e-12f;
        float nx = fmaxf(sqrtf(sxx), eps);
        float nc = fmaxf(sqrtf(scc), eps);
        float d = sxx / (nx * nx) + scc / (nc * nc) - 2.0f * sxc / (nx * nc);
        d = fminf(fmaxf(d, 1e-12f), 1e12f);
        s_dist[warp] = d;
    }
    __syncthreads();

    __shared__ bool s_last;
    if (threadIdx.x == 0) {
        float s = 0.f;
        #pragma unroll
        for (int w = 0; w < WARPS_PER_BLOCK; ++w) s += s_dist[w];
        g_partials[blockIdx.x] = s;
        __threadfence();
        unsigned int ticket = atomicAdd(&g_count, 1u);
        s_last = (ticket == NBLOCKS - 1);
    }
    __syncthreads();

    if (s_last) {
        // Deterministic final reduction over 2048 partials (L2-resident).
        __shared__ float sm[THREADS];
        float s = 0.f;
        #pragma unroll
        for (int i = threadIdx.x; i < NBLOCKS; i += THREADS) s += g_partials[i];
        sm[threadIdx.x] = s;
        __syncthreads();
        #pragma unroll
        for (int stride = THREADS / 2; stride > 0; stride >>= 1) {
            if (threadIdx.x < stride) sm[threadIdx.x] += sm[threadIdx.x + stride];
            __syncthreads();
        }
        if (threadIdx.x == 0) {
            out[0] = sm[0] * (1.0f / (float)B_ROWS);
            g_count = 0;
        }
    }
}

extern "C" void kernel_launch(void* const* d_in, const int* in_sizes, int n_in,
                              void* d_out, int out_size)
{
    const float* x       = (const float*)d_in[0];
    const int*   labels  = (const int*)d_in[1];
    const float* centers = (const float*)d_in[2];
    float*       out     = (float*)d_out;

    proximity_fused_kernel<<<NBLOCKS, THREADS>>>(x, labels, centers, out);
}